// round 17
// baseline (speedup 1.0000x reference)
#include <cuda_runtime.h>
#include <cuda_fp16.h>
#include <math.h>
#include <stdint.h>

#define NB   8
#define IMG  512

// ---------------------------------------------------------------------------
// Scratch (static device globals — no allocations allowed)
// ---------------------------------------------------------------------------
__device__ float g_gray  [NB*IMG*IMG];
__device__ float g_lap   [NB*IMG*IMG];
__device__ float g_flags [NB*127*127];
__device__ float g_maskR [NB*64*64];
__device__ float g_maskD [NB*64*64];
__device__ __half g_th   [NB*256*64*64];   // conv output scratch, fp16
__device__ float g_spmean[NB*64*64];
__device__ float g_spmax [NB*64*64];
__device__ float g_sw    [NB*64*64];
__device__ float g_gap   [NB*1024];
__device__ float g_cw    [NB*1024];
__device__ float g_bnA   [1024];
__device__ float g_bnB   [1024];
__device__ float g_bnSum [1024];
__device__ float g_bnSq  [1024];
__device__ int   g_anyR;
__device__ int   g_anyD;

// aux activations fp16, halo-padded NHWC [b][S+2][S+2][C] (max 8*66*66*256)
__device__ __half g_auxh[8921088];
// Winograd F(2x2,3x3) buffers:
//   U [k=16][co][ci] fp16           (max 16*1024*1024)
//   V [k=16][n=b*T+t][ci] fp16      (max 16*8192*256)
//   M [k=16][co][n] fp16            (max 16*256*8192)
__device__ __half g_U[16*1024*1024];
__device__ __half g_V[16*8192*256];
__device__ __half g_M[16*256*8192];

// ---------------------------------------------------------------------------
// MMA + cp.async helpers (legacy mma.sync path — tcgen05 rejected by the
// harness's compute_100 lowering; legacy HMMA runs ~quarter-rate on sm_100,
// hence Winograd to cut mma count 2.25x)
// ---------------------------------------------------------------------------
__device__ __forceinline__ uint32_t smem_u32(const void* p) {
    return (uint32_t)__cvta_generic_to_shared(p);
}
__device__ __forceinline__ void ldsm4(uint32_t* r, uint32_t addr) {
    asm volatile("ldmatrix.sync.aligned.m8n8.x4.shared.b16 {%0,%1,%2,%3}, [%4];"
                 : "=r"(r[0]), "=r"(r[1]), "=r"(r[2]), "=r"(r[3]) : "r"(addr));
}
__device__ __forceinline__ void ldsm2(uint32_t* r, uint32_t addr) {
    asm volatile("ldmatrix.sync.aligned.m8n8.x2.shared.b16 {%0,%1}, [%2];"
                 : "=r"(r[0]), "=r"(r[1]) : "r"(addr));
}
__device__ __forceinline__ void mma16816h(float* c, const uint32_t* a, const uint32_t* b) {
    asm volatile("mma.sync.aligned.m16n8k16.row.col.f32.f16.f16.f32 "
                 "{%0,%1,%2,%3}, {%4,%5,%6,%7}, {%8,%9}, {%0,%1,%2,%3};"
                 : "+f"(c[0]), "+f"(c[1]), "+f"(c[2]), "+f"(c[3])
                 : "r"(a[0]), "r"(a[1]), "r"(a[2]), "r"(a[3]), "r"(b[0]), "r"(b[1]));
}
__device__ __forceinline__ void cpa16(uint32_t dst, const void* src) {
    asm volatile("cp.async.cg.shared.global [%0], [%1], 16;" :: "r"(dst), "l"(src));
}
__device__ __forceinline__ void cpa_commit() { asm volatile("cp.async.commit_group;"); }
__device__ __forceinline__ void cpa_wait1()  { asm volatile("cp.async.wait_group 1;"); }
__device__ __forceinline__ void cpa_wait0()  { asm volatile("cp.async.wait_group 0;"); }

// ---------------------------------------------------------------------------
// Stage A: blur mask from rgb image + depth mask
// ---------------------------------------------------------------------------
__global__ void k_zeroflags() { g_anyR = 0; g_anyD = 0; }

__global__ void k_gray(const float* __restrict__ rgb) {
    int idx = blockIdx.x * blockDim.x + threadIdx.x;
    if (idx >= NB*IMG*IMG) return;
    int b = idx / (IMG*IMG);
    int p = idx - b * (IMG*IMG);
    const float* base = rgb + (size_t)b * 3 * IMG * IMG;
    float g = 0.299f*base[p] + 0.587f*base[IMG*IMG + p] + 0.114f*base[2*IMG*IMG + p];
    g *= 255.0f;
    g = fminf(fmaxf(g, 0.0f), 255.0f);
    g_gray[idx] = g;
}

__global__ void k_lap() {
    int idx = blockIdx.x * blockDim.x + threadIdx.x;
    if (idx >= NB*IMG*IMG) return;
    int b = idx / (IMG*IMG);
    int p = idx - b * (IMG*IMG);
    int y = p / IMG, x = p - y * IMG;
    const float* g = g_gray + (size_t)b * IMG * IMG;
    float c = g[y*IMG + x];
    float u = (y > 0)       ? g[(y-1)*IMG + x] : 0.0f;
    float d = (y < IMG-1)   ? g[(y+1)*IMG + x] : 0.0f;
    float l = (x > 0)       ? g[y*IMG + x-1]   : 0.0f;
    float r = (x < IMG-1)   ? g[y*IMG + x+1]   : 0.0f;
    g_lap[idx] = u + d + l + r - 4.0f*c;
}

__global__ void k_flags() {
    int idx = blockIdx.x * blockDim.x + threadIdx.x;
    if (idx >= NB*127*127) return;
    int b = idx / (127*127);
    int rem = idx - b * (127*127);
    int i = rem / 127, j = rem - i * 127;
    const float* lp = g_lap + (size_t)b * IMG * IMG + (4*i)*IMG + 4*j;
    float s1 = 0.0f, s2 = 0.0f;
    #pragma unroll
    for (int dy = 0; dy < 8; dy++) {
        #pragma unroll
        for (int dx = 0; dx < 8; dx++) {
            float v = lp[dy*IMG + dx];
            s1 += v; s2 += v*v;
        }
    }
    float var = (s2 - s1*s1*(1.0f/64.0f)) * (1.0f/63.0f);
    g_flags[idx] = (var < 50.0f) ? 1.0f : 0.0f;
}

__global__ void k_masks(const float* __restrict__ depth) {
    int idx = blockIdx.x * blockDim.x + threadIdx.x;
    if (idx >= NB*64*64) return;
    int b = idx / (64*64);
    int rem = idx - b * (64*64);
    int k = rem / 64, l = rem - k * 64;
    float f = 0.0f;
    #pragma unroll
    for (int da = 0; da < 2; da++) {
        int a = 2*k - da;
        if (a < 0) continue;
        #pragma unroll
        for (int db = 0; db < 2; db++) {
            int bb = 2*l - db;
            if (bb < 0) continue;
            f = fmaxf(f, g_flags[((size_t)b*127 + a)*127 + bb]);
        }
    }
    g_maskR[idx] = f;
    float dv = depth[((size_t)b*3 + 2)*IMG*IMG + (8*k)*IMG + 8*l];
    float md = (dv <= 0.0f) ? 1.0f : 0.0f;
    g_maskD[idx] = md;
    if (f  > 0.0f) atomicOr(&g_anyR, 1);
    if (md > 0.0f) atomicOr(&g_anyD, 1);
}

// ---------------------------------------------------------------------------
// Layout kernels
// ---------------------------------------------------------------------------
// Zero only the halo border of the padded NHWC aux (interior fully
// overwritten by k_cvtaux_pad). Border cells per image: 2*S2 + 2*S.
__global__ void k_zero_border(int C, int S, int useRmask) {
    if ((useRmask ? g_anyR : g_anyD) == 0) return;
    int S2 = S + 2;
    int nb = 2 * S2 + 2 * S;              // border cells per image
    int C8 = C / 8;
    int total = NB * nb * C8;
    int i = blockIdx.x * blockDim.x + threadIdx.x;
    if (i >= total) return;
    int c8 = i % C8;
    int rem = i / C8;
    int cell = rem % nb;
    int b = rem / nb;
    int y, x;
    if (cell < S2)            { y = 0;        x = cell; }
    else if (cell < 2*S2)     { y = S + 1;    x = cell - S2; }
    else if (cell < 2*S2 + S) { y = 1 + (cell - 2*S2);       x = 0; }
    else                      { y = 1 + (cell - 2*S2 - S);   x = S + 1; }
    size_t o = (((size_t)b * S2 + y) * S2 + x) * C + c8 * 8;
    uint4 z = {0, 0, 0, 0};
    *(uint4*)(g_auxh + o) = z;
}

__global__ void k_cvtaux_pad(const float* __restrict__ aux, int C, int S,
                             int useRmask) {
    if ((useRmask ? g_anyR : g_anyD) == 0) return;
    __shared__ float tile[32][33];
    int S32 = (S + 31) / 32;
    int xt = blockIdx.x % S32;
    int ct = blockIdx.x / S32;
    int y  = blockIdx.y;
    int b  = blockIdx.z;
    int tx = threadIdx.x & 31;
    int tg = threadIdx.x >> 5;
    int S2 = S + 2;
    for (int cc = tg; cc < 32; cc += 8) {
        int x = xt * 32 + tx, c = ct * 32 + cc;
        float v = 0.0f;
        if (x < S) v = aux[(((size_t)b * C + c) * S + y) * S + x];
        tile[cc][tx] = v;
    }
    __syncthreads();
    for (int xx = tg; xx < 32; xx += 8) {
        int x = xt * 32 + xx, c = ct * 32 + tx;
        if (x < S) {
            size_t o = (((size_t)b * S2 + y + 1) * S2 + x + 1) * C + c;
            g_auxh[o] = __float2half_rn(tile[tx][xx]);
        }
    }
}

// ---------------------------------------------------------------------------
// Winograd F(2x2,3x3) transforms
// ---------------------------------------------------------------------------
__global__ void k_wino_w(const float* __restrict__ w, int C) {
    if (g_anyR == 0 && g_anyD == 0) return;
    int idx = blockIdx.x * blockDim.x + threadIdx.x;
    if (idx >= C * C) return;
    int co = idx / C, ci = idx - co * C;
    const float* gp = w + ((size_t)co * C + ci) * 9;
    float g[3][3];
    #pragma unroll
    for (int i = 0; i < 3; i++)
        #pragma unroll
        for (int j = 0; j < 3; j++) g[i][j] = gp[i*3 + j];
    float q[4][3];
    #pragma unroll
    for (int j = 0; j < 3; j++) {
        q[0][j] = g[0][j];
        q[1][j] = 0.5f * (g[0][j] + g[1][j] + g[2][j]);
        q[2][j] = 0.5f * (g[0][j] - g[1][j] + g[2][j]);
        q[3][j] = g[2][j];
    }
    #pragma unroll
    for (int i = 0; i < 4; i++) {
        float u0 = q[i][0];
        float u1 = 0.5f * (q[i][0] + q[i][1] + q[i][2]);
        float u2 = 0.5f * (q[i][0] - q[i][1] + q[i][2]);
        float u3 = q[i][2];
        g_U[((size_t)(i*4 + 0) * C + co) * C + ci] = __float2half_rn(u0);
        g_U[((size_t)(i*4 + 1) * C + co) * C + ci] = __float2half_rn(u1);
        g_U[((size_t)(i*4 + 2) * C + co) * C + ci] = __float2half_rn(u2);
        g_U[((size_t)(i*4 + 3) * C + co) * C + ci] = __float2half_rn(u3);
    }
}

__global__ void k_wino_in(int C, int S, int T, int NBT, int useRmask) {
    if ((useRmask ? g_anyR : g_anyD) == 0) return;
    int idx = blockIdx.x * blockDim.x + threadIdx.x;
    if (idx >= NBT * C) return;
    int ci = idx % C;
    int n  = idx / C;
    int b  = n / T;
    int t  = n - b * T;
    int W  = S >> 1;
    int ty = t / W, tx = t - ty * W;
    int S2 = S + 2;
    const __half* src = g_auxh + (((size_t)b * S2 + 2*ty) * S2 + 2*tx) * C + ci;
    float d[4][4];
    #pragma unroll
    for (int i = 0; i < 4; i++)
        #pragma unroll
        for (int j = 0; j < 4; j++)
            d[i][j] = __half2float(src[((size_t)i * S2 + j) * C]);
    float a[4][4];
    #pragma unroll
    for (int j = 0; j < 4; j++) {
        a[0][j] = d[0][j] - d[2][j];
        a[1][j] = d[1][j] + d[2][j];
        a[2][j] = d[2][j] - d[1][j];
        a[3][j] = d[1][j] - d[3][j];
    }
    #pragma unroll
    for (int i = 0; i < 4; i++) {
        float v0 = a[i][0] - a[i][2];
        float v1 = a[i][1] + a[i][2];
        float v2 = a[i][2] - a[i][1];
        float v3 = a[i][1] - a[i][3];
        g_V[((size_t)(i*4 + 0) * NBT + n) * C + ci] = __float2half_rn(v0);
        g_V[((size_t)(i*4 + 1) * NBT + n) * C + ci] = __float2half_rn(v1);
        g_V[((size_t)(i*4 + 2) * NBT + n) * C + ci] = __float2half_rn(v2);
        g_V[((size_t)(i*4 + 3) * NBT + n) * C + ci] = __float2half_rn(v3);
    }
}

// ---------------------------------------------------------------------------
// 16 batched GEMMs (grid.z = k): M_k[co][n] = U_k[co][:] . V_k[n][:]
// CTA: 64 co x 256 n, 8 warps (2M x 4N, warp = 32co x 64n), K-chunk 32.
// fp16 mma, fp32 accum, fp16 M output. Double-buffered cp.async.
// smem rows padded to 40 elems (80B) -> conflict-free ldmatrix.
// ---------------------------------------------------------------------------
#define WROW 40
#define WA_ELEMS (64*WROW)            // 2560
#define WB_ELEMS (256*WROW)           // 10240
#define WSTAGE (WA_ELEMS + WB_ELEMS)  // 12800
#define WSMEM_BYTES (2*WSTAGE*2)      // 51200

template<int C>
__global__ void __launch_bounds__(256) k_wino_mm(int NBT, int useRmask) {
    if ((useRmask ? g_anyR : g_anyD) == 0) return;

    extern __shared__ __align__(16) char smem_raw[];
    const uint32_t sm0 = smem_u32(smem_raw);

    const int k      = blockIdx.z;
    const int coBase = blockIdx.y * 64;
    const int nBase  = blockIdx.x * 256;

    const int tid  = threadIdx.x;
    const int lane = tid & 31;
    const int wid  = tid >> 5;
    const int wm   = wid & 1;       // 2 x 32co
    const int wn   = wid >> 1;      // 4 x 64n

    const __half* Ubase = g_U + (size_t)k * C * C;
    const __half* Vbase = g_V + (size_t)k * NBT * C;

    const int aM = ((lane >> 3) & 1) * 8 + (lane & 7);
    const int aK = (lane >> 4) * 8;
    const int lb = lane & 15;
    const int bRow = lb & 7;
    const int bK   = (lb >> 3) * 8;

    float acc[2][8][4];
    #pragma unroll
    for (int mf = 0; mf < 2; mf++)
        #pragma unroll
        for (int nf = 0; nf < 8; nf++)
            #pragma unroll
            for (int q = 0; q < 4; q++) acc[mf][nf][q] = 0.0f;

    constexpr int NCHUNK = C / 32;

    auto fill = [&](int s, int ci0) {
        uint32_t base = sm0 + (uint32_t)(s * WSTAGE) * 2;
        // A: 64 rows x 32 ci = 256 16B-chunks
        for (int i = tid; i < 256; i += 256) {
            int row = i >> 2, j = i & 3;
            cpa16(base + (uint32_t)(row * WROW + j * 8) * 2,
                  Ubase + ((size_t)(coBase + row)) * C + ci0 + j * 8);
        }
        // B: 256 rows x 32 ci = 1024 16B-chunks
        uint32_t bb = base + (uint32_t)WA_ELEMS * 2;
        for (int i = tid; i < 1024; i += 256) {
            int row = i >> 2, j = i & 3;
            cpa16(bb + (uint32_t)(row * WROW + j * 8) * 2,
                  Vbase + ((size_t)(nBase + row)) * C + ci0 + j * 8);
        }
    };

    fill(0, 0);
    cpa_commit();

    for (int kk = 0; kk < NCHUNK; kk++) {
        int s = kk & 1;
        if (kk + 1 < NCHUNK) {
            fill(s ^ 1, (kk + 1) * 32);
            cpa_commit();
            cpa_wait1();
        } else {
            cpa_wait0();
        }
        __syncthreads();

        const uint32_t base = sm0 + (uint32_t)(s * WSTAGE) * 2;
        const uint32_t sA32 = base;
        const uint32_t sB32 = base + (uint32_t)WA_ELEMS * 2;

        #pragma unroll
        for (int ks = 0; ks < 2; ks++) {
            uint32_t Af[2][4];
            #pragma unroll
            for (int mf = 0; mf < 2; mf++) {
                int ea = (wm * 32 + mf * 16 + aM) * WROW + ks * 16 + aK;
                ldsm4(Af[mf], sA32 + ea * 2);
            }
            #pragma unroll
            for (int nf = 0; nf < 8; nf++) {
                int eb = (wn * 64 + nf * 8 + bRow) * WROW + ks * 16 + bK;
                uint32_t Bf[2];
                ldsm2(Bf, sB32 + eb * 2);
                #pragma unroll
                for (int mf = 0; mf < 2; mf++)
                    mma16816h(acc[mf][nf], Af[mf], Bf);
            }
        }
        __syncthreads();
    }

    // epilogue: M[k][co][n] fp16
    __half* Mb = g_M + (size_t)k * C * NBT;
    #pragma unroll
    for (int mf = 0; mf < 2; mf++) {
        #pragma unroll
        for (int nf = 0; nf < 8; nf++) {
            int co = coBase + wm * 32 + mf * 16 + (lane >> 2);
            int n  = nBase + wn * 64 + nf * 8 + (lane & 3) * 2;
            __half2 lo = __floats2half2_rn(acc[mf][nf][0], acc[mf][nf][1]);
            __half2 hi = __floats2half2_rn(acc[mf][nf][2], acc[mf][nf][3]);
            *(__half2*)(Mb + (size_t)co * NBT + n) = lo;
            *(__half2*)(Mb + (size_t)(co + 8) * NBT + n) = hi;
        }
    }
}

// Zero BN accumulators (per direction)
__global__ void k_zero_bn(int C, int useRmask) {
    if ((useRmask ? g_anyR : g_anyD) == 0) return;
    int i = blockIdx.x * blockDim.x + threadIdx.x;
    if (i >= C) return;
    g_bnSum[i] = 0.0f;
    g_bnSq[i]  = 0.0f;
}

// Output: o = A^T m A -> 2x2 per (co, tile) into g_th NCHW (fp16),
// with fused per-channel BN sum/sumsq accumulation (warp-uniform co:
// idx = co*NBT + n, NBT multiple of 32, so each warp is one channel).
__global__ void k_wino_out(int C, int S, int T, int NBT, int useRmask) {
    if ((useRmask ? g_anyR : g_anyD) == 0) return;
    int idx = blockIdx.x * blockDim.x + threadIdx.x;
    if (idx >= C * NBT) return;
    int n  = idx % NBT;
    int co = idx / NBT;
    int b  = n / T;
    int t  = n - b * T;
    int W  = S >> 1;
    int ty = t / W, tx = t - ty * W;

    float m[4][4];
    #pragma unroll
    for (int i = 0; i < 4; i++)
        #pragma unroll
        for (int j = 0; j < 4; j++)
            m[i][j] = __half2float(g_M[((size_t)(i*4 + j) * C + co) * NBT + n]);

    float r[2][4];
    #pragma unroll
    for (int j = 0; j < 4; j++) {
        r[0][j] = m[0][j] + m[1][j] + m[2][j];
        r[1][j] = m[1][j] - m[2][j] - m[3][j];
    }
    float o00 = r[0][0] + r[0][1] + r[0][2];
    float o01 = r[0][1] - r[0][2] - r[0][3];
    float o10 = r[1][0] + r[1][1] + r[1][2];
    float o11 = r[1][1] - r[1][2] - r[1][3];

    __half* dst = g_th + (((size_t)b * C + co) * S + 2*ty) * S + 2*tx;
    *(__half2*)dst       = __floats2half2_rn(o00, o01);
    *(__half2*)(dst + S) = __floats2half2_rn(o10, o11);

    // fused BN statistics (warp-uniform channel)
    float s = o00 + o01 + o10 + o11;
    float q = o00*o00 + o01*o01 + o10*o10 + o11*o11;
    #pragma unroll
    for (int o = 16; o > 0; o >>= 1) {
        s += __shfl_xor_sync(0xFFFFFFFF, s, o);
        q += __shfl_xor_sync(0xFFFFFFFF, q, o);
    }
    if ((threadIdx.x & 31) == 0) {
        atomicAdd(&g_bnSum[co], s);
        atomicAdd(&g_bnSq[co],  q);
    }
}

// Finalize BN: bnA/bnB from accumulated sums
__global__ void k_bnfin(const float* __restrict__ gamma,
                        const float* __restrict__ beta, int C, int S,
                        int useRmask) {
    if ((useRmask ? g_anyR : g_anyD) == 0) return;
    int c = blockIdx.x * blockDim.x + threadIdx.x;
    if (c >= C) return;
    float n = (float)(NB * S * S);
    float mean = g_bnSum[c] / n;
    float var  = g_bnSq[c] / n - mean * mean;
    float rstd = 1.0f / sqrtf(var + 1e-5f);
    float A = gamma[c] * rstd;
    g_bnA[c] = A;
    g_bnB[c] = beta[c] - mean * A;
}

// ---------------------------------------------------------------------------
// Spatial attention: per-pixel channel mean/max (coalesced), 7x7 conv + sigmoid
// ---------------------------------------------------------------------------
__global__ void k_spstats(const float* __restrict__ mainp, int C, int S,
                          int useRmask) {
    if ((useRmask ? g_anyR : g_anyD) == 0) return;
    int b = blockIdx.y;
    int p = blockIdx.x * blockDim.x + threadIdx.x;
    if (p >= S*S) return;
    const float* base = mainp + (size_t)b*C*S*S + p;
    float m = 0.0f, mx = -3.402823466e38f;
    #pragma unroll 4
    for (int c = 0; c < C; c++) {
        float v = base[(size_t)c*S*S];
        m += v; mx = fmaxf(mx, v);
    }
    g_spmean[(size_t)b*S*S + p] = m / (float)C;
    g_spmax [(size_t)b*S*S + p] = mx;
}

__global__ void k_spconv(const float* __restrict__ saw, int S, int useRmask) {
    if ((useRmask ? g_anyR : g_anyD) == 0) return;
    __shared__ float sw_[196];
    int b = blockIdx.y, y = blockIdx.x, x = threadIdx.x;
    for (int i = x; i < 196; i += blockDim.x) sw_[i] = saw[i];
    __syncthreads();
    float step = 2.0f / (float)(S - 1);
    float acc = 0.0f;
    #pragma unroll
    for (int ky = 0; ky < 7; ky++) {
        int yy = y + ky - 3;
        if (yy < 0 || yy >= S) continue;
        #pragma unroll
        for (int kx = 0; kx < 7; kx++) {
            int xx = x + kx - 3;
            if (xx < 0 || xx >= S) continue;
            int widx = ky*7 + kx;
            acc += sw_[widx]        * g_spmean[(size_t)b*S*S + yy*S + xx];
            acc += sw_[49 + widx]   * g_spmax [(size_t)b*S*S + yy*S + xx];
            acc += sw_[98 + widx]   * (-1.0f + (float)xx * step);
            acc += sw_[147 + widx]  * (-1.0f + (float)yy * step);
        }
    }
    g_sw[(size_t)b*S*S + y*S + x] = 1.0f / (1.0f + expf(-acc));
}

// ---------------------------------------------------------------------------
// Channel attention: GAP -> ca1 -> relu -> ca2 -> sigmoid
// ---------------------------------------------------------------------------
__global__ void k_gap(const float* __restrict__ mainp, int C, int S,
                      int useRmask) {
    if ((useRmask ? g_anyR : g_anyD) == 0) return;
    int c = blockIdx.x, b = blockIdx.y;
    const float* p = mainp + ((size_t)b*C + c)*S*S;
    float s = 0.0f;
    for (int i = threadIdx.x; i < S*S; i += 128) s += p[i];
    __shared__ float sm[128];
    sm[threadIdx.x] = s;
    __syncthreads();
    for (int o = 64; o > 0; o >>= 1) {
        if (threadIdx.x < o) sm[threadIdx.x] += sm[threadIdx.x + o];
        __syncthreads();
    }
    if (threadIdx.x == 0) g_gap[b*C + c] = sm[0] / (float)(S*S);
}

__global__ void k_ca(const float* __restrict__ ca1, const float* __restrict__ ca2,
                     int C, int Rr, int useRmask) {
    if ((useRmask ? g_anyR : g_anyD) == 0) return;
    int b = blockIdx.x;
    __shared__ float sg[1024];
    __shared__ float sh[64];
    for (int c = threadIdx.x; c < C; c += 128) sg[c] = g_gap[b*C + c];
    __syncthreads();
    for (int rr = threadIdx.x; rr < Rr; rr += 128) {
        float h = 0.0f;
        for (int c = 0; c < C; c++) h += ca1[(size_t)rr*C + c] * sg[c];
        sh[rr] = fmaxf(h, 0.0f);
    }
    __syncthreads();
    for (int c = threadIdx.x; c < C; c += 128) {
        float v = 0.0f;
        for (int rr = 0; rr < Rr; rr++) v += ca2[(size_t)c*Rr + rr] * sh[rr];
        g_cw[b*C + c] = 1.0f / (1.0f + expf(-v));
    }
}

// ---------------------------------------------------------------------------
// Final blend: out = (inv==0) ? main : 2 * relu(A*t+B) * sw * cw
// ---------------------------------------------------------------------------
__global__ void k_final(const float* __restrict__ mainp, float* __restrict__ outp,
                        int C, int S, int step, int useRmask) {
    int idx = blockIdx.x * blockDim.x + threadIdx.x;
    int N = NB * C * S * S;
    if (idx >= N) return;
    int b   = idx / (C*S*S);
    int rem = idx - b * (C*S*S);
    int c   = rem / (S*S);
    int p   = rem - c * (S*S);
    int y = p / S, x = p - y * S;
    const float* maskp = useRmask ? g_maskR : g_maskD;
    float inv = maskp[((size_t)b*64 + y*step)*64 + x*step];
    float res;
    if (inv == 0.0f) {
        res = mainp[idx];
    } else {
        float tv = __half2float(g_th[idx]);
        float a  = fmaxf(g_bnA[c]*tv + g_bnB[c], 0.0f);
        res = ((a * g_sw[(size_t)b*S*S + p]) * g_cw[b*C + c]) * 2.0f;
    }
    outp[idx] = res;
}

// ---------------------------------------------------------------------------
// Host orchestration
// ---------------------------------------------------------------------------
struct LvlParams {
    const float *ft, *g, *b, *sa, *ca1, *ca2;
};

template<int C, int S>
static void run_dir(const float* mainp, const float* auxp, int useRmask,
                    float* outp, const LvlParams& P) {
    int S2 = S + 2;
    int nBorder = NB * (2*S2 + 2*S) * (C/8);
    k_zero_border<<<(nBorder + 255)/256, 256>>>(C, S, useRmask);
    int S32 = (S + 31) / 32;
    k_cvtaux_pad<<<dim3(S32 * (C/32), S, NB), 256>>>(auxp, C, S, useRmask);

    constexpr int T = (S/2) * (S/2);
    constexpr int NBT = NB * T;
    k_wino_in<<<(NBT * C + 255)/256, 256>>>(C, S, T, NBT, useRmask);
    cudaFuncSetAttribute(k_wino_mm<C>,
                         cudaFuncAttributeMaxDynamicSharedMemorySize, WSMEM_BYTES);
    dim3 mgrid(NBT/256, C/64, 16);
    k_wino_mm<C><<<mgrid, 256, WSMEM_BYTES>>>(NBT, useRmask);
    k_zero_bn<<<(C + 255)/256, 256>>>(C, useRmask);
    k_wino_out<<<(C * NBT + 255)/256, 256>>>(C, S, T, NBT, useRmask);
    k_bnfin<<<(C + 255)/256, 256>>>(P.g, P.b, C, S, useRmask);

    k_spstats<<<dim3((S*S + 255)/256, NB), 256>>>(mainp, C, S, useRmask);
    k_spconv<<<dim3(S, NB), S>>>(P.sa, S, useRmask);
    k_gap<<<dim3(C, NB), 128>>>(mainp, C, S, useRmask);
    k_ca<<<NB, 128>>>(P.ca1, P.ca2, C, C/16, useRmask);
    int N = NB * C * S * S;
    k_final<<<(N + 255)/256, 256>>>(mainp, outp, C, S, 64/S, useRmask);
}

extern "C" void kernel_launch(void* const* d_in, const int* in_sizes, int n_in,
                              void* d_out, int out_size) {
    // metadata order follows setup_inputs() dict insertion order:
    // rgb_feat0, depth_feat0, rgb_feat1, depth_feat1, rgb_feat2, depth_feat2,
    // rgb_img, depth_img, then per level: ft_w, bn_g, bn_b, sa_w, ca1_w, ca2_w
    const float* rgbF[3] = {(const float*)d_in[0], (const float*)d_in[2], (const float*)d_in[4]};
    const float* depF[3] = {(const float*)d_in[1], (const float*)d_in[3], (const float*)d_in[5]};
    const float* rgb_img   = (const float*)d_in[6];
    const float* depth_img = (const float*)d_in[7];
    LvlParams P[3];
    for (int i = 0; i < 3; i++) {
        int base = 8 + i*6;
        P[i].ft  = (const float*)d_in[base + 0];
        P[i].g   = (const float*)d_in[base + 1];
        P[i].b   = (const float*)d_in[base + 2];
        P[i].sa  = (const float*)d_in[base + 3];
        P[i].ca1 = (const float*)d_in[base + 4];
        P[i].ca2 = (const float*)d_in[base + 5];
    }
    float* out = (float*)d_out;

    // masks
    int npix = NB * IMG * IMG;
    k_zeroflags<<<1, 1>>>();
    k_gray <<<(npix + 255)/256, 256>>>(rgb_img);
    k_lap  <<<(npix + 255)/256, 256>>>();
    k_flags<<<(NB*127*127 + 255)/256, 256>>>();
    k_masks<<<(NB*64*64 + 255)/256, 256>>>(depth_img);

    const size_t szR0 = (size_t)NB*256*64*64;
    const size_t szR1 = (size_t)NB*512*32*32;
    const size_t szR2 = (size_t)NB*1024*16*16;
    float* oR0 = out;
    float* oR1 = oR0 + szR0;
    float* oR2 = oR1 + szR1;
    float* oD0 = oR2 + szR2;
    float* oD1 = oD0 + szR0;
    float* oD2 = oD1 + szR1;

    // level 0
    k_wino_w<<<(256*256 + 255)/256, 256>>>(P[0].ft, 256);
    run_dir<256, 64>(rgbF[0], depF[0], 1, oR0, P[0]);
    run_dir<256, 64>(depF[0], rgbF[0], 0, oD0, P[0]);
    // level 1
    k_wino_w<<<(512*512 + 255)/256, 256>>>(P[1].ft, 512);
    run_dir<512, 32>(rgbF[1], depF[1], 1, oR1, P[1]);
    run_dir<512, 32>(depF[1], rgbF[1], 0, oD1, P[1]);
    // level 2
    k_wino_w<<<(1024*1024 + 255)/256, 256>>>(P[2].ft, 1024);
    run_dir<1024,16>(rgbF[2], depF[2], 1, oR2, P[2]);
    run_dir<1024,16>(depF[2], rgbF[2], 0, oD2, P[2]);
}